// round 2
// baseline (speedup 1.0000x reference)
#include <cuda_runtime.h>
#include <math.h>

// Problem constants
#define NN 4
#define C1 128
#define C2 36
#define Hh 192
#define Ww 192
#define HO 190
#define WO 190
#define HW (Hh*Ww)
#define HWO (HO*WO)
#define HALF (HWO/2)   // 18050

// Scratch (device globals: allocation-free rule)
__device__ float g_offset[NN*C2*HO*WO];   // offset conv output [N,36,HO,WO]
__device__ float g_wt[9*C1*C2];           // deform_w transposed [tap][c][o], BN-scaled
__device__ float g_bias[C2];              // folded BN bias

// ---------------------------------------------------------------------------
// Prep: transpose deform_w [o][c][3][3] -> g_wt[tap][c][o], folding BN scale.
// ---------------------------------------------------------------------------
__global__ void prep_kernel(const float* __restrict__ dw,
                            const float* __restrict__ gamma,
                            const float* __restrict__ beta,
                            const float* __restrict__ mean,
                            const float* __restrict__ var)
{
    int idx = blockIdx.x * 256 + threadIdx.x;
    if (idx < 9 * C1 * C2) {
        int t = idx / (C1 * C2);
        int r = idx % (C1 * C2);
        int c = r / C2, o = r % C2;
        float s = gamma[o] * rsqrtf(var[o] + 1e-5f);
        g_wt[idx] = dw[(o * C1 + c) * 9 + t] * s;
    }
    if (idx < C2) {
        float s = gamma[idx] * rsqrtf(var[idx] + 1e-5f);
        g_bias[idx] = beta[idx] - mean[idx] * s;
    }
}

// ---------------------------------------------------------------------------
// Offset-generating grouped conv (groups=4, VALID, 3x3, stride 1)
// Block: 192 threads = 32x6 pixel tile, 2 output rows per thread (12 rows).
// Weights padded to 12 floats per (ci,tap) for float4 LDS.
// ---------------------------------------------------------------------------
__global__ __launch_bounds__(192) void offset_conv_kernel(
    const float* __restrict__ x, const float* __restrict__ cw)
{
    __shared__ float  sx[16 * 14 * 34];   // 16-ch chunk, 14 rows, 34 cols (30.5KB)
    __shared__ float4 wsv[32 * 9 * 3];    // [ci][tap][12 floats] (13.8KB)

    int n = blockIdx.z >> 2;
    int g = blockIdx.z & 3;
    int x0 = blockIdx.x * 32;
    int y0 = blockIdx.y * 12;
    int tid = threadIdx.x;

    // stage padded weights: wsv linear idx = (ci*9+tap)*12 + o
    float* wsf = (float*)wsv;
    for (int idx = tid; idx < 32 * 9 * 12; idx += 192) {
        int o = idx % 12; int rem = idx / 12;
        int tap = rem % 9; int ci = rem / 9;
        wsf[idx] = (o < 9) ? cw[((g * 9 + o) * 32 + ci) * 9 + tap] : 0.f;
    }

    int lx = tid & 31, ly = tid >> 5;   // ly in 0..5
    float acc[18];
#pragma unroll
    for (int o = 0; o < 18; o++) acc[o] = 0.f;

    for (int chunk = 0; chunk < 2; chunk++) {
        __syncthreads();
        const float* xb = x + ((size_t)n * C1 + g * 32 + chunk * 16) * HW;
        for (int idx = tid; idx < 16 * 14 * 34; idx += 192) {
            int ci = idx / 476;           // 14*34
            int r  = (idx % 476) / 34;
            int col = idx % 34;
            int gy = y0 + r, gx = x0 + col;
            float v = 0.f;
            if (gy < Hh && gx < Ww) v = xb[ci * HW + gy * Ww + gx];
            sx[idx] = v;
        }
        __syncthreads();

        for (int ci = 0; ci < 16; ci++) {
            int base = ci * 476 + ly * 34 + lx;
            const float4* wp = wsv + ((chunk * 16 + ci) * 9) * 3;
#pragma unroll
            for (int tap = 0; tap < 9; tap++) {
                int i = tap / 3, j = tap % 3;
                float va = sx[base + i * 34 + j];
                float vb = sx[base + (i + 6) * 34 + j];
                float4 w0 = wp[tap * 3 + 0];
                float4 w1 = wp[tap * 3 + 1];
                float4 w2 = wp[tap * 3 + 2];
                acc[0] = fmaf(va, w0.x, acc[0]);
                acc[1] = fmaf(va, w0.y, acc[1]);
                acc[2] = fmaf(va, w0.z, acc[2]);
                acc[3] = fmaf(va, w0.w, acc[3]);
                acc[4] = fmaf(va, w1.x, acc[4]);
                acc[5] = fmaf(va, w1.y, acc[5]);
                acc[6] = fmaf(va, w1.z, acc[6]);
                acc[7] = fmaf(va, w1.w, acc[7]);
                acc[8] = fmaf(va, w2.x, acc[8]);
                acc[9]  = fmaf(vb, w0.x, acc[9]);
                acc[10] = fmaf(vb, w0.y, acc[10]);
                acc[11] = fmaf(vb, w0.z, acc[11]);
                acc[12] = fmaf(vb, w0.w, acc[12]);
                acc[13] = fmaf(vb, w1.x, acc[13]);
                acc[14] = fmaf(vb, w1.y, acc[14]);
                acc[15] = fmaf(vb, w1.z, acc[15]);
                acc[16] = fmaf(vb, w1.w, acc[16]);
                acc[17] = fmaf(vb, w2.x, acc[17]);
            }
        }
    }

    int xx = x0 + lx;
    int ya = y0 + ly;           // always < 190 (<=185)
    int yb = y0 + ly + 6;       // may be >= 190
    if (xx < WO) {
        float* op = g_offset + ((size_t)n * C2 + g * 9) * HWO;
#pragma unroll
        for (int o = 0; o < 9; o++)
            op[o * HWO + ya * WO + xx] = acc[o];
        if (yb < HO) {
#pragma unroll
            for (int o = 0; o < 9; o++)
                op[o * HWO + yb * WO + xx] = acc[9 + o];
        }
    }
}

// ---------------------------------------------------------------------------
// Deformable conv + folded BN + Mish.
// Each thread handles TWO output pixels (p and p+HWO/2) so each weight
// float4 LDS feeds 8 FMAs. Next-channel corner loads are prefetched.
// ---------------------------------------------------------------------------
struct Ctx {
    int o00, o01, o10, o11;
    float W00, W01, W10, W11;
};

__device__ __forceinline__ Ctx make_ctx(int yy, int xx, int i, int j,
                                        float dy, float dx)
{
    Ctx c;
    float py = (float)(yy + i) + dy;
    float px = (float)(xx + j) + dx;
    float fy0 = floorf(py), fx0 = floorf(px);
    float wy1 = py - fy0, wx1 = px - fx0;
    float wy0 = 1.f - wy1, wx0 = 1.f - wx1;

    bool vy0 = (fy0       >= 0.f) && (fy0       <= (float)(Hh - 1));
    bool vy1 = (fy0 + 1.f >= 0.f) && (fy0 + 1.f <= (float)(Hh - 1));
    bool vx0 = (fx0       >= 0.f) && (fx0       <= (float)(Ww - 1));
    bool vx1 = (fx0 + 1.f >= 0.f) && (fx0 + 1.f <= (float)(Ww - 1));

    int y0i = (int)fy0, x0i = (int)fx0;
    int y0c = min(max(y0i,     0), Hh - 1);
    int y1c = min(max(y0i + 1, 0), Hh - 1);
    int x0c = min(max(x0i,     0), Ww - 1);
    int x1c = min(max(x0i + 1, 0), Ww - 1);

    c.W00 = wy0 * wx0 * ((vy0 && vx0) ? 1.f : 0.f);
    c.W01 = wy0 * wx1 * ((vy0 && vx1) ? 1.f : 0.f);
    c.W10 = wy1 * wx0 * ((vy1 && vx0) ? 1.f : 0.f);
    c.W11 = wy1 * wx1 * ((vy1 && vx1) ? 1.f : 0.f);

    c.o00 = y0c * Ww + x0c; c.o01 = y0c * Ww + x1c;
    c.o10 = y1c * Ww + x0c; c.o11 = y1c * Ww + x1c;
    return c;
}

__global__ __launch_bounds__(128, 3) void deform_kernel(
    const float* __restrict__ x, float* __restrict__ out)
{
    __shared__ float4 wts[1152];   // per-tap weights [c=128][o=36] = 9 float4/c

    int n = blockIdx.y;
    int p0 = blockIdx.x * 128 + threadIdx.x;
    bool active = (p0 < HALF);
    int pa = active ? p0 : 0;
    int pb = pa + HALF;
    int ya = pa / WO, xa = pa % WO;
    int yb = pb / WO, xb2 = pb % WO;

    const float* xbase = x + (size_t)n * C1 * HW;
    const float* offa = g_offset + (size_t)n * C2 * HWO + pa;
    const float* offb = g_offset + (size_t)n * C2 * HWO + pb;
    const float4* gwt4 = (const float4*)g_wt;

    float acc0[36], acc1[36];
#pragma unroll
    for (int o = 0; o < 36; o++) { acc0[o] = 0.f; acc1[o] = 0.f; }

    for (int t = 0; t < 9; t++) {
        __syncthreads();
        for (int idx = threadIdx.x; idx < 1152; idx += 128)
            wts[idx] = gwt4[t * 1152 + idx];
        __syncthreads();

        int i = t / 3, j = t % 3;
#pragma unroll
        for (int dg = 0; dg < 2; dg++) {
            float dya = offa[(dg * 18 + t * 2    ) * HWO];
            float dxa = offa[(dg * 18 + t * 2 + 1) * HWO];
            float dyb = offb[(dg * 18 + t * 2    ) * HWO];
            float dxb = offb[(dg * 18 + t * 2 + 1) * HWO];
            Ctx A = make_ctx(ya, xa, i, j, dya, dxa);
            Ctx B = make_ctx(yb, xb2, i, j, dyb, dxb);

            const float*  pc = xbase + dg * 64 * HW;
            const float4* wb = wts + dg * 64 * 9;

            float a00 = __ldg(pc + A.o00), a01 = __ldg(pc + A.o01);
            float a10 = __ldg(pc + A.o10), a11 = __ldg(pc + A.o11);
            float b00 = __ldg(pc + B.o00), b01 = __ldg(pc + B.o01);
            float b10 = __ldg(pc + B.o10), b11 = __ldg(pc + B.o11);

            for (int c = 0; c < 64; c++) {
                float na00, na01, na10, na11, nb00, nb01, nb10, nb11;
                if (c < 63) {
                    const float* q = pc + (c + 1) * HW;
                    na00 = __ldg(q + A.o00); na01 = __ldg(q + A.o01);
                    na10 = __ldg(q + A.o10); na11 = __ldg(q + A.o11);
                    nb00 = __ldg(q + B.o00); nb01 = __ldg(q + B.o01);
                    nb10 = __ldg(q + B.o10); nb11 = __ldg(q + B.o11);
                } else {
                    na00=na01=na10=na11=nb00=nb01=nb10=nb11 = 0.f;
                }
                float v0 = fmaf(A.W00, a00, fmaf(A.W01, a01,
                           fmaf(A.W10, a10, A.W11 * a11)));
                float v1 = fmaf(B.W00, b00, fmaf(B.W01, b01,
                           fmaf(B.W10, b10, B.W11 * b11)));

                const float4* wp = wb + c * 9;
#pragma unroll
                for (int q = 0; q < 9; q++) {
                    float4 wv = wp[q];
                    acc0[q*4+0] = fmaf(v0, wv.x, acc0[q*4+0]);
                    acc0[q*4+1] = fmaf(v0, wv.y, acc0[q*4+1]);
                    acc0[q*4+2] = fmaf(v0, wv.z, acc0[q*4+2]);
                    acc0[q*4+3] = fmaf(v0, wv.w, acc0[q*4+3]);
                    acc1[q*4+0] = fmaf(v1, wv.x, acc1[q*4+0]);
                    acc1[q*4+1] = fmaf(v1, wv.y, acc1[q*4+1]);
                    acc1[q*4+2] = fmaf(v1, wv.z, acc1[q*4+2]);
                    acc1[q*4+3] = fmaf(v1, wv.w, acc1[q*4+3]);
                }
                a00=na00; a01=na01; a10=na10; a11=na11;
                b00=nb00; b01=nb01; b10=nb10; b11=nb11;
            }
        }
    }

    if (active) {
        float* oa = out + (size_t)n * C2 * HWO + pa;
        float* ob = out + (size_t)n * C2 * HWO + pb;
#pragma unroll
        for (int o = 0; o < 36; o++) {
            float b = __ldg(g_bias + o);
            float z0 = acc0[o] + b;
            float z1 = acc1[o] + b;
            float sp0 = (z0 > 20.f) ? z0 : log1pf(expf(z0));
            float sp1 = (z1 > 20.f) ? z1 : log1pf(expf(z1));
            oa[o * HWO] = z0 * tanhf(sp0);
            ob[o * HWO] = z1 * tanhf(sp1);
        }
    }
}

// ---------------------------------------------------------------------------
extern "C" void kernel_launch(void* const* d_in, const int* in_sizes, int n_in,
                              void* d_out, int out_size)
{
    const float* x        = (const float*)d_in[0];
    const float* conv_w   = (const float*)d_in[1];
    const float* deform_w = (const float*)d_in[2];
    const float* bn_gamma = (const float*)d_in[3];
    const float* bn_beta  = (const float*)d_in[4];
    const float* bn_mean  = (const float*)d_in[5];
    const float* bn_var   = (const float*)d_in[6];
    float* out = (float*)d_out;

    prep_kernel<<<(9 * C1 * C2 + 255) / 256, 256>>>(
        deform_w, bn_gamma, bn_beta, bn_mean, bn_var);

    // offset conv: 32x12 output tiles -> grid (6, 16, 16)
    offset_conv_kernel<<<dim3(6, 16, 16), 192>>>(x, conv_w);

    // deform conv: 2 pixels/thread, 18050 pairs per image
    deform_kernel<<<dim3((HALF + 127) / 128, NN), 128>>>(x, out);
}